// round 1
// baseline (speedup 1.0000x reference)
#include <cuda_runtime.h>
#include <math.h>

// Problem constants
#define NROWS 8192
#define DIM   256
#define BATCH 4096
// 1/T = 10 ; 1/(T*ln2) for exp2-domain sum-exp
#define INV_T      10.0f
#define INV_T_LN2  14.4269504088896340736f

// Scratch in device globals (no allocations allowed)
__device__ float g_zn [NROWS * DIM];   // normalized rows, row-major
__device__ float g_znT[DIM * NROWS];   // transposed copy for coalesced tile loads
__device__ float g_rowsum[NROWS];      // sum_{j!=i} exp(sim_ij)

__device__ __forceinline__ float ex2(float x) {
    asm("ex2.approx.f32 %0, %0;" : "+f"(x));
    return x;
}

// ---------------------------------------------------------------------------
// Kernel 1: normalize rows, build zn and znT, zero rowsum and output.
// 256 threads / block, block handles 32 rows (each warp: 4 rows).
// ---------------------------------------------------------------------------
__global__ void k_prep(const float* __restrict__ z, float* __restrict__ out) {
    __shared__ float s[32][257];
    const int r0   = blockIdx.x * 32;
    const int w    = threadIdx.x >> 5;
    const int lane = threadIdx.x & 31;

    for (int q = 0; q < 4; q++) {
        const int row = r0 + w * 4 + q;
        const float4* zr = reinterpret_cast<const float4*>(z + row * DIM);
        float4 a = zr[lane];
        float4 b = zr[32 + lane];
        float ss = a.x*a.x + a.y*a.y + a.z*a.z + a.w*a.w
                 + b.x*b.x + b.y*b.y + b.z*b.z + b.w*b.w;
        #pragma unroll
        for (int o = 16; o; o >>= 1) ss += __shfl_xor_sync(0xffffffffu, ss, o);
        const float sc = rsqrtf(ss);
        a.x *= sc; a.y *= sc; a.z *= sc; a.w *= sc;
        b.x *= sc; b.y *= sc; b.z *= sc; b.w *= sc;

        float4* znr = reinterpret_cast<float4*>(g_zn + row * DIM);
        znr[lane]      = a;
        znr[32 + lane] = b;

        const int rl = w * 4 + q;
        const int d0 = lane * 4;
        s[rl][d0 + 0] = a.x; s[rl][d0 + 1] = a.y;
        s[rl][d0 + 2] = a.z; s[rl][d0 + 3] = a.w;
        s[rl][128 + d0 + 0] = b.x; s[rl][128 + d0 + 1] = b.y;
        s[rl][128 + d0 + 2] = b.z; s[rl][128 + d0 + 3] = b.w;

        if (lane == 0) g_rowsum[row] = 0.0f;
    }
    __syncthreads();

    // Coalesced transposed writes: 32 consecutive rows at a given d.
    const int rloc  = threadIdx.x & 31;
    const int dbase = threadIdx.x >> 5;  // 0..7
    #pragma unroll
    for (int d = dbase; d < DIM; d += 8)
        g_znT[d * NROWS + r0 + rloc] = s[rloc][d];

    if (blockIdx.x == 0 && threadIdx.x == 0) out[0] = 0.0f;
}

// ---------------------------------------------------------------------------
// Kernel 2: symmetric sim GEMM + exp + rowsum scatter.
// 128x128 tile per CTA, 256 threads, 8x8 register tile, K-chunks of 16,
// double-buffered smem. Only bj >= bi tiles are computed; off-diagonal tiles
// contribute exp to BOTH rowsum[i] and rowsum[j].
// ---------------------------------------------------------------------------
#define TM 128
#define TK 16

__global__ void __launch_bounds__(256, 2) k_sim() {
    const int bi = blockIdx.y, bj = blockIdx.x;
    if (bj < bi) return;
    const bool diag = (bi == bj);

    __shared__ float As[2][TK][TM];
    __shared__ float Bs[2][TK][TM];

    const int i0 = bi * TM, j0 = bj * TM;
    const int t  = threadIdx.x;
    const int tx = t & 15;        // column sub-tile
    const int ty = t >> 4;        // row sub-tile (also the k-row this thread loads)
    const int lm = tx * 8;        // 8 floats this thread loads per smem row

    const float* pA = g_znT + ty * NROWS + i0 + lm;
    const float* pB = g_znT + ty * NROWS + j0 + lm;

    float acc[8][8];
    #pragma unroll
    for (int r = 0; r < 8; r++)
        #pragma unroll
        for (int c = 0; c < 8; c++) acc[r][c] = 0.0f;

    // preload chunk 0
    {
        float4 a0 = *reinterpret_cast<const float4*>(pA);
        float4 a1 = *reinterpret_cast<const float4*>(pA + 4);
        float4 b0 = *reinterpret_cast<const float4*>(pB);
        float4 b1 = *reinterpret_cast<const float4*>(pB + 4);
        *reinterpret_cast<float4*>(&As[0][ty][lm])     = a0;
        *reinterpret_cast<float4*>(&As[0][ty][lm + 4]) = a1;
        *reinterpret_cast<float4*>(&Bs[0][ty][lm])     = b0;
        *reinterpret_cast<float4*>(&Bs[0][ty][lm + 4]) = b1;
    }
    __syncthreads();

    const int NCHUNK = DIM / TK;  // 16
    #pragma unroll 1
    for (int c = 0; c < NCHUNK; c++) {
        const int cur = c & 1, nxt = cur ^ 1;
        float4 pa0, pa1, pb0, pb1;
        if (c < NCHUNK - 1) {
            const float* qA = pA + (c + 1) * TK * NROWS;
            const float* qB = pB + (c + 1) * TK * NROWS;
            pa0 = *reinterpret_cast<const float4*>(qA);
            pa1 = *reinterpret_cast<const float4*>(qA + 4);
            pb0 = *reinterpret_cast<const float4*>(qB);
            pb1 = *reinterpret_cast<const float4*>(qB + 4);
        }
        #pragma unroll
        for (int k = 0; k < TK; k++) {
            float4 a0 = *reinterpret_cast<const float4*>(&As[cur][k][ty * 8]);
            float4 a1 = *reinterpret_cast<const float4*>(&As[cur][k][ty * 8 + 4]);
            float4 b0 = *reinterpret_cast<const float4*>(&Bs[cur][k][tx * 8]);
            float4 b1 = *reinterpret_cast<const float4*>(&Bs[cur][k][tx * 8 + 4]);
            float a[8] = {a0.x, a0.y, a0.z, a0.w, a1.x, a1.y, a1.z, a1.w};
            float b[8] = {b0.x, b0.y, b0.z, b0.w, b1.x, b1.y, b1.z, b1.w};
            #pragma unroll
            for (int r = 0; r < 8; r++)
                #pragma unroll
                for (int s2 = 0; s2 < 8; s2++)
                    acc[r][s2] += a[r] * b[s2];
        }
        if (c < NCHUNK - 1) {
            *reinterpret_cast<float4*>(&As[nxt][ty][lm])     = pa0;
            *reinterpret_cast<float4*>(&As[nxt][ty][lm + 4]) = pa1;
            *reinterpret_cast<float4*>(&Bs[nxt][ty][lm])     = pb0;
            *reinterpret_cast<float4*>(&Bs[nxt][ty][lm + 4]) = pb1;
        }
        __syncthreads();
    }

    // Epilogue: exp in exp2 domain, per-thread row/col partials.
    float rsum[8], csum[8];
    #pragma unroll
    for (int r = 0; r < 8; r++) { rsum[r] = 0.0f; csum[r] = 0.0f; }
    #pragma unroll
    for (int r = 0; r < 8; r++) {
        #pragma unroll
        for (int s2 = 0; s2 < 8; s2++) {
            float e = ex2(acc[r][s2] * INV_T_LN2);
            if (diag && (ty * 8 + r) == (tx * 8 + s2)) e = 0.0f;
            rsum[r] += e;
            csum[s2] += e;
        }
    }

    // Cross-thread reduction through smem (reuse As).
    float* red = &As[0][0][0];   // 4096 floats available; need 2048

    __syncthreads();   // everyone done reading As
    #pragma unroll
    for (int r = 0; r < 8; r++) red[(ty * 8 + r) * 16 + tx] = rsum[r];
    __syncthreads();
    if (t < 128) {
        float v = 0.0f;
        #pragma unroll
        for (int x = 0; x < 16; x++) v += red[t * 16 + x];
        atomicAdd(&g_rowsum[i0 + t], v);
    }
    __syncthreads();
    if (!diag) {
        #pragma unroll
        for (int s2 = 0; s2 < 8; s2++) red[(tx * 8 + s2) * 16 + ty] = csum[s2];
        __syncthreads();
        if (t < 128) {
            float v = 0.0f;
            #pragma unroll
            for (int x = 0; x < 16; x++) v += red[t * 16 + x];
            atomicAdd(&g_rowsum[j0 + t], v);
        }
    }
}

// ---------------------------------------------------------------------------
// Kernel 3: pos logits + final reduction. One warp per row.
// ---------------------------------------------------------------------------
__global__ void k_loss(float* __restrict__ out) {
    const int row  = blockIdx.x * 8 + (threadIdx.x >> 5);
    const int lane = threadIdx.x & 31;
    const int p    = (row < BATCH) ? row + BATCH : row - BATCH;

    const float4* a4 = reinterpret_cast<const float4*>(g_zn + row * DIM);
    const float4* b4 = reinterpret_cast<const float4*>(g_zn + p * DIM);
    float4 a0 = a4[lane], a1 = a4[32 + lane];
    float4 b0 = b4[lane], b1 = b4[32 + lane];
    float dot = a0.x*b0.x + a0.y*b0.y + a0.z*b0.z + a0.w*b0.w
              + a1.x*b1.x + a1.y*b1.y + a1.z*b1.z + a1.w*b1.w;
    #pragma unroll
    for (int o = 16; o; o >>= 1) dot += __shfl_xor_sync(0xffffffffu, dot, o);

    if (lane == 0) {
        const float pos = dot * INV_T;
        const float val = logf(g_rowsum[row]) - pos;
        atomicAdd(out, val * (1.0f / (float)NROWS));
    }
}

// ---------------------------------------------------------------------------
extern "C" void kernel_launch(void* const* d_in, const int* in_sizes, int n_in,
                              void* d_out, int out_size) {
    const float* z = (const float*)d_in[0];
    float* out = (float*)d_out;

    k_prep<<<NROWS / 32, 256>>>(z, out);
    dim3 grid(NROWS / TM, NROWS / TM);
    k_sim<<<grid, 256>>>();
    k_loss<<<NROWS / 8, 256>>>(out);
}

// round 4
// speedup vs baseline: 5.1654x; 5.1654x over previous
#include <cuda_runtime.h>
#include <cuda_bf16.h>
#include <math.h>
#include <stdint.h>

// Problem constants
#define NROWS 8192
#define DIM   256
#define BATCH 4096
#define INV_T      10.0f
#define INV_T_LN2  14.4269504088896340736f

#define NB        64                   // 8192 / 128 tiles per side
#define NTRI      (NB * (NB + 1) / 2)  // 2080 triangular CTAs

// Device-global scratch (no allocations allowed)
__device__ float          g_zn [NROWS * DIM];   // normalized rows fp32 (pos dots)
__device__ __nv_bfloat16  g_znb[NROWS * DIM];   // normalized rows bf16 (MMA operands)
__device__ float          g_rowsum[NROWS];      // sum_{j!=i} exp(sim_ij)

// ---------------------------------------------------------------------------
__device__ __forceinline__ uint32_t smem_u32(const void* p) {
    uint32_t a;
    asm("{ .reg .u64 t; cvta.to.shared.u64 t, %1; cvt.u32.u64 %0, t; }" : "=r"(a) : "l"(p));
    return a;
}
__device__ __forceinline__ float ex2(float x) {
    asm("ex2.approx.f32 %0, %0;" : "+f"(x));
    return x;
}
#define CP_ASYNC16(s, g) \
    asm volatile("cp.async.cg.shared.global [%0], [%1], 16;" :: "r"(s), "l"(g) : "memory")
#define CP_COMMIT() asm volatile("cp.async.commit_group;" ::: "memory")
#define CP_WAIT(n)  asm volatile("cp.async.wait_group %0;" :: "n"(n) : "memory")

#define LDSM_X4(r0, r1, r2, r3, addr) \
    asm volatile("ldmatrix.sync.aligned.m8n8.x4.shared.b16 {%0,%1,%2,%3}, [%4];" \
                 : "=r"(r0), "=r"(r1), "=r"(r2), "=r"(r3) : "r"(addr))

#define MMA16816(c0, c1, c2, c3, a0, a1, a2, a3, b0, b1) \
    asm volatile("mma.sync.aligned.m16n8k16.row.col.f32.bf16.bf16.f32 " \
                 "{%0,%1,%2,%3}, {%4,%5,%6,%7}, {%8,%9}, {%0,%1,%2,%3};" \
                 : "+f"(c0), "+f"(c1), "+f"(c2), "+f"(c3) \
                 : "r"(a0), "r"(a1), "r"(a2), "r"(a3), "r"(b0), "r"(b1))

// ---------------------------------------------------------------------------
// Kernel 1: normalize rows -> g_zn (fp32) + g_znb (bf16); zero rowsum/out.
// ---------------------------------------------------------------------------
__global__ void k_prep(const float* __restrict__ z, float* __restrict__ out) {
    const int row  = blockIdx.x * 8 + (threadIdx.x >> 5);
    const int lane = threadIdx.x & 31;

    const float4* zr = reinterpret_cast<const float4*>(z + row * DIM);
    float4 a = zr[lane * 2];
    float4 b = zr[lane * 2 + 1];
    float ss = a.x*a.x + a.y*a.y + a.z*a.z + a.w*a.w
             + b.x*b.x + b.y*b.y + b.z*b.z + b.w*b.w;
    #pragma unroll
    for (int o = 16; o; o >>= 1) ss += __shfl_xor_sync(0xffffffffu, ss, o);
    const float sc = rsqrtf(ss);
    a.x *= sc; a.y *= sc; a.z *= sc; a.w *= sc;
    b.x *= sc; b.y *= sc; b.z *= sc; b.w *= sc;

    float4* o4 = reinterpret_cast<float4*>(g_zn + row * DIM);
    o4[lane * 2]     = a;
    o4[lane * 2 + 1] = b;

    __nv_bfloat162 p0 = __floats2bfloat162_rn(a.x, a.y);
    __nv_bfloat162 p1 = __floats2bfloat162_rn(a.z, a.w);
    __nv_bfloat162 p2 = __floats2bfloat162_rn(b.x, b.y);
    __nv_bfloat162 p3 = __floats2bfloat162_rn(b.z, b.w);
    uint4 pk;
    pk.x = *reinterpret_cast<uint32_t*>(&p0);
    pk.y = *reinterpret_cast<uint32_t*>(&p1);
    pk.z = *reinterpret_cast<uint32_t*>(&p2);
    pk.w = *reinterpret_cast<uint32_t*>(&p3);
    *reinterpret_cast<uint4*>(g_znb + row * DIM + lane * 8) = pk;

    if (lane == 0) g_rowsum[row] = 0.0f;
    if (row == 0 && lane == 0) out[0] = 0.0f;
}

// ---------------------------------------------------------------------------
// Kernel 2: symmetric bf16 tensor-core sim GEMM + exp + rowsum.
// Triangular grid (bj >= bi). CTA: 128x128 tile, 8 warps (2x4), warp 64x32.
// K=256 in 4 slabs of 64 (128B rows, SW-style xor swizzle), cp.async
// double-buffered. Accumulators in registers -> fused exp epilogue with
// row sums (rowsum[i]) and, off-diagonal, column sums (rowsum[j]).
// ---------------------------------------------------------------------------
#define SLAB_BYTES 16384            // 128 rows x 128B (64 bf16)
#define BUF_BYTES  (2 * SLAB_BYTES) // A + B
#define DYN_SMEM   (2 * BUF_BYTES)  // double buffered = 64 KB

__global__ void __launch_bounds__(256) k_sim() {
    extern __shared__ char dyn_smem[];
    const uint32_t smem = smem_u32(dyn_smem);

    // Triangular decode: blockIdx.x -> (bi, bj), bj >= bi.
    const int id = blockIdx.x;
    int bi = (int)(64.5f - sqrtf(64.5f * 64.5f - 2.0f * (float)id));
    // fix-up for fp rounding
    while (bi * NB - bi * (bi - 1) / 2 > id) bi--;
    while ((bi + 1) * NB - (bi + 1) * bi / 2 <= id) bi++;
    const int bj = bi + (id - (bi * NB - bi * (bi - 1) / 2));
    const bool diag = (bi == bj);
    const int i0 = bi * 128, j0 = bj * 128;

    const int tid  = threadIdx.x;
    const int lane = tid & 31;
    const int wid  = tid >> 5;
    const int wm   = wid >> 2;       // 0..1 : warp row  (64 rows each)
    const int wn   = wid & 3;        // 0..3 : warp col  (32 cols each)

    const __nv_bfloat16* Ag = g_znb + (size_t)i0 * DIM;
    const __nv_bfloat16* Bg = g_znb + (size_t)j0 * DIM;

    // Per-thread gmem->smem mapping: 8 iters x (A chunk + B chunk).
    const int ldr = tid >> 1;              // 0..127 : row handled (2 chunks/row/thread-pair)
    // Each slab row is 128B = 8 x 16B chunks; 256 threads * 4 = 1024 chunks per tile.
    // Simpler mapping: idx = tid + it*256 over 1024 chunks: r = idx>>3, c = idx&7.
    (void)ldr;

    auto issue_slab = [&](int s, int buf) {
        const uint32_t abase = smem + (uint32_t)buf * BUF_BYTES;
        const uint32_t bbase = abase + SLAB_BYTES;
        #pragma unroll
        for (int it = 0; it < 4; it++) {
            const int idx = tid + it * 256;          // 0..1023
            const int r = idx >> 3, c = idx & 7;
            const uint32_t soff = (uint32_t)(r * 128 + ((c ^ (r & 7)) << 4));
            CP_ASYNC16(abase + soff, (const char*)(Ag + r * DIM + s * 64 + c * 8));
            CP_ASYNC16(bbase + soff, (const char*)(Bg + r * DIM + s * 64 + c * 8));
        }
        CP_COMMIT();
    };

    float acc[4][4][4];
    #pragma unroll
    for (int mt = 0; mt < 4; mt++)
        #pragma unroll
        for (int nt = 0; nt < 4; nt++)
            #pragma unroll
            for (int r = 0; r < 4; r++) acc[mt][nt][r] = 0.0f;

    // ldmatrix per-thread source rows/halves
    const int ar    = lane & 15;           // A: row within 16-row tile
    const int ahalf = lane >> 4;           // A: k half (0/1)
    const int bn    = ((lane >> 4) & 1) * 8 + (lane & 7);  // B: n row within 16
    const int bhalf = (lane >> 3) & 1;     // B: k half

    issue_slab(0, 0);

    #pragma unroll 1
    for (int s = 0; s < 4; s++) {
        if (s < 3) issue_slab(s + 1, (s + 1) & 1);
        if (s < 3) { CP_WAIT(1); } else { CP_WAIT(0); }
        __syncthreads();

        const uint32_t abase = smem + (uint32_t)(s & 1) * BUF_BYTES;
        const uint32_t bbase = abase + SLAB_BYTES;

        #pragma unroll
        for (int kk = 0; kk < 4; kk++) {
            // B fragments: 2 x ldmatrix.x4 -> 4 n-tiles (8 cols each)
            uint32_t bfr[4][2];
            #pragma unroll
            for (int p = 0; p < 2; p++) {
                const int row = wn * 32 + p * 16 + bn;
                const int ch  = kk * 2 + bhalf;
                const uint32_t ad = bbase + (uint32_t)(row * 128 + ((ch ^ (row & 7)) << 4));
                LDSM_X4(bfr[2*p][0], bfr[2*p][1], bfr[2*p+1][0], bfr[2*p+1][1], ad);
            }
            // A fragments + MMAs per m-tile
            #pragma unroll
            for (int mt = 0; mt < 4; mt++) {
                const int row = wm * 64 + mt * 16 + ar;
                const int ch  = kk * 2 + ahalf;
                const uint32_t ad = abase + (uint32_t)(row * 128 + ((ch ^ (row & 7)) << 4));
                uint32_t a0, a1, a2, a3;
                LDSM_X4(a0, a1, a2, a3, ad);
                #pragma unroll
                for (int nt = 0; nt < 4; nt++) {
                    MMA16816(acc[mt][nt][0], acc[mt][nt][1], acc[mt][nt][2], acc[mt][nt][3],
                             a0, a1, a2, a3, bfr[nt][0], bfr[nt][1]);
                }
            }
        }
        __syncthreads();  // all warps done reading this buffer before it is refilled
    }

    // ------------------------- epilogue -------------------------
    // acc[mt][nt][r]: r0/r1 -> row lane/4,      cols (lane%4)*2 + {0,1}
    //                 r2/r3 -> row lane/4 + 8,  same cols
    float rsum[8];   // [mt*2 + h] : rows wm*64 + mt*16 + h*8 + lane/4
    float csum[8];   // [nt*2 + e] : cols wn*32 + nt*8 + (lane%4)*2 + e
    #pragma unroll
    for (int i = 0; i < 8; i++) { rsum[i] = 0.0f; csum[i] = 0.0f; }

    const int q = lane >> 2;      // 0..7
    const int e2 = (lane & 3) * 2;

    #pragma unroll
    for (int mt = 0; mt < 4; mt++) {
        #pragma unroll
        for (int nt = 0; nt < 4; nt++) {
            #pragma unroll
            for (int r = 0; r < 4; r++) {
                const int h   = r >> 1;            // row half
                const int e   = r & 1;             // col element
                float v = ex2(acc[mt][nt][r] * INV_T_LN2);
                if (diag) {
                    const int rl = wm * 64 + mt * 16 + h * 8 + q;
                    const int cl = wn * 32 + nt * 8 + e2 + e;
                    if (rl == cl) v = 0.0f;
                }
                rsum[mt * 2 + h] += v;
                csum[nt * 2 + e] += v;
            }
        }
    }

    // Row reduce: 4 threads per row (lane%4). shfl over bits 0,1.
    #pragma unroll
    for (int i = 0; i < 8; i++) {
        rsum[i] += __shfl_xor_sync(0xffffffffu, rsum[i], 1);
        rsum[i] += __shfl_xor_sync(0xffffffffu, rsum[i], 2);
    }
    // Col reduce: 8 threads per col (lane/4). shfl over bits 2,3,4.
    #pragma unroll
    for (int i = 0; i < 8; i++) {
        csum[i] += __shfl_xor_sync(0xffffffffu, csum[i], 4);
        csum[i] += __shfl_xor_sync(0xffffffffu, csum[i], 8);
        csum[i] += __shfl_xor_sync(0xffffffffu, csum[i], 16);
    }

    float* sred = reinterpret_cast<float*>(dyn_smem);            // [128][4]
    float* cred = sred + 128 * 4;                                 // [128][2]

    if ((lane & 3) == 0) {
        #pragma unroll
        for (int i = 0; i < 8; i++) {
            const int mt = i >> 1, h = i & 1;
            const int rl = wm * 64 + mt * 16 + h * 8 + q;
            sred[rl * 4 + wn] = rsum[i];
        }
    }
    if (!diag && (lane >> 2) == 0) {
        #pragma unroll
        for (int i = 0; i < 8; i++) {
            const int nt = i >> 1, e = i & 1;
            const int cl = wn * 32 + nt * 8 + (lane & 3) * 2 + e;
            cred[cl * 2 + wm] = csum[i];
        }
    }
    __syncthreads();

    if (tid < 128) {
        const float v = sred[tid * 4 + 0] + sred[tid * 4 + 1]
                      + sred[tid * 4 + 2] + sred[tid * 4 + 3];
        atomicAdd(&g_rowsum[i0 + tid], v);
        if (!diag) {
            const float w = cred[tid * 2 + 0] + cred[tid * 2 + 1];
            atomicAdd(&g_rowsum[j0 + tid], w);
        }
    }
}

// ---------------------------------------------------------------------------
// Kernel 3: pos logits (fp32) + final reduction. One warp per row.
// ---------------------------------------------------------------------------
__global__ void k_loss(float* __restrict__ out) {
    const int row  = blockIdx.x * 8 + (threadIdx.x >> 5);
    const int lane = threadIdx.x & 31;
    const int p    = (row < BATCH) ? row + BATCH : row - BATCH;

    const float4* a4 = reinterpret_cast<const float4*>(g_zn + row * DIM);
    const float4* b4 = reinterpret_cast<const float4*>(g_zn + p * DIM);
    float4 a0 = a4[lane * 2], a1 = a4[lane * 2 + 1];
    float4 b0 = b4[lane * 2], b1 = b4[lane * 2 + 1];
    float dot = a0.x*b0.x + a0.y*b0.y + a0.z*b0.z + a0.w*b0.w
              + a1.x*b1.x + a1.y*b1.y + a1.z*b1.z + a1.w*b1.w;
    #pragma unroll
    for (int o = 16; o; o >>= 1) dot += __shfl_xor_sync(0xffffffffu, dot, o);

    if (lane == 0) {
        const float pos = dot * INV_T;
        const float val = logf(g_rowsum[row]) - pos;
        atomicAdd(out, val * (1.0f / (float)NROWS));
    }
}

// ---------------------------------------------------------------------------
extern "C" void kernel_launch(void* const* d_in, const int* in_sizes, int n_in,
                              void* d_out, int out_size) {
    const float* z = (const float*)d_in[0];
    float* out = (float*)d_out;

    cudaFuncSetAttribute(k_sim, cudaFuncAttributeMaxDynamicSharedMemorySize, DYN_SMEM);

    k_prep<<<NROWS / 8, 256>>>(z, out);
    k_sim<<<NTRI, 256, DYN_SMEM>>>();
    k_loss<<<NROWS / 8, 256>>>(out);
}

// round 5
// speedup vs baseline: 6.5970x; 1.2772x over previous
#include <cuda_runtime.h>
#include <cuda_bf16.h>
#include <math.h>
#include <stdint.h>

// Problem constants
#define NROWS 8192
#define DIM   256
#define BATCH 4096
#define INV_T      10.0f
#define INV_T_LN2  14.4269504088896340736f

#define NB        64                   // 8192 / 128 tiles per side
#define NTRI      (NB * (NB + 1) / 2)  // 2080 triangular CTAs

// Device-global scratch (no allocations allowed)
__device__ __nv_bfloat16  g_znb[NROWS * DIM];   // normalized rows bf16 (MMA operands)
__device__ float          g_rowsum[NROWS];      // sum_{j!=i} exp(sim_ij)
__device__ float          g_pos[BATCH];         // cos(z_i, z_{i+B})  (shared by both rows)

// ---------------------------------------------------------------------------
__device__ __forceinline__ uint32_t smem_u32(const void* p) {
    uint32_t a;
    asm("{ .reg .u64 t; cvta.to.shared.u64 t, %1; cvt.u32.u64 %0, t; }" : "=r"(a) : "l"(p));
    return a;
}
__device__ __forceinline__ float ex2(float x) {
    asm("ex2.approx.f32 %0, %0;" : "+f"(x));
    return x;
}
#define CP_ASYNC16(s, g) \
    asm volatile("cp.async.cg.shared.global [%0], [%1], 16;" :: "r"(s), "l"(g) : "memory")
#define CP_COMMIT() asm volatile("cp.async.commit_group;" ::: "memory")
#define CP_WAIT(n)  asm volatile("cp.async.wait_group %0;" :: "n"(n) : "memory")

#define LDSM_X4(r0, r1, r2, r3, addr) \
    asm volatile("ldmatrix.sync.aligned.m8n8.x4.shared.b16 {%0,%1,%2,%3}, [%4];" \
                 : "=r"(r0), "=r"(r1), "=r"(r2), "=r"(r3) : "r"(addr))

#define MMA16816(c0, c1, c2, c3, a0, a1, a2, a3, b0, b1) \
    asm volatile("mma.sync.aligned.m16n8k16.row.col.f32.bf16.bf16.f32 " \
                 "{%0,%1,%2,%3}, {%4,%5,%6,%7}, {%8,%9}, {%0,%1,%2,%3};" \
                 : "+f"(c0), "+f"(c1), "+f"(c2), "+f"(c3) \
                 : "r"(a0), "r"(a1), "r"(a2), "r"(a3), "r"(b0), "r"(b1))

// ---------------------------------------------------------------------------
// Kernel 1: normalize rows -> g_znb (bf16), pos dots -> g_pos, zero rowsum.
// Block: 256 threads = 8 warps; warps 0-3 handle rows r0..r0+3, warps 4-7
// their partners r0+BATCH..; pos computed through smem once per pair.
// ---------------------------------------------------------------------------
__global__ void k_prep(const float* __restrict__ z, float* __restrict__ out) {
    __shared__ float sa[4][256];
    const int w    = threadIdx.x >> 5;
    const int lane = threadIdx.x & 31;
    const int pr   = w & 3;
    const bool second = (w >= 4);
    const int row = blockIdx.x * 4 + pr + (second ? BATCH : 0);

    const float4* zr = reinterpret_cast<const float4*>(z + row * DIM);
    float4 a = zr[lane * 2];
    float4 b = zr[lane * 2 + 1];
    float ss = a.x*a.x + a.y*a.y + a.z*a.z + a.w*a.w
             + b.x*b.x + b.y*b.y + b.z*b.z + b.w*b.w;
    #pragma unroll
    for (int o = 16; o; o >>= 1) ss += __shfl_xor_sync(0xffffffffu, ss, o);
    const float sc = rsqrtf(ss);
    a.x *= sc; a.y *= sc; a.z *= sc; a.w *= sc;
    b.x *= sc; b.y *= sc; b.z *= sc; b.w *= sc;

    __nv_bfloat162 p0 = __floats2bfloat162_rn(a.x, a.y);
    __nv_bfloat162 p1 = __floats2bfloat162_rn(a.z, a.w);
    __nv_bfloat162 p2 = __floats2bfloat162_rn(b.x, b.y);
    __nv_bfloat162 p3 = __floats2bfloat162_rn(b.z, b.w);
    uint4 pk;
    pk.x = *reinterpret_cast<uint32_t*>(&p0);
    pk.y = *reinterpret_cast<uint32_t*>(&p1);
    pk.z = *reinterpret_cast<uint32_t*>(&p2);
    pk.w = *reinterpret_cast<uint32_t*>(&p3);
    *reinterpret_cast<uint4*>(g_znb + row * DIM + lane * 8) = pk;

    if (!second) {
        float4* s4 = reinterpret_cast<float4*>(&sa[pr][lane * 8]);
        s4[0] = a; s4[1] = b;
    }
    __syncthreads();
    if (second) {
        const float* sp = &sa[pr][lane * 8];
        float dot = a.x*sp[0] + a.y*sp[1] + a.z*sp[2] + a.w*sp[3]
                  + b.x*sp[4] + b.y*sp[5] + b.z*sp[6] + b.w*sp[7];
        #pragma unroll
        for (int o = 16; o; o >>= 1) dot += __shfl_xor_sync(0xffffffffu, dot, o);
        if (lane == 0) g_pos[blockIdx.x * 4 + pr] = dot;
    }
    if (lane == 0) g_rowsum[row] = 0.0f;
    if (row == 0 && lane == 0) out[0] = 0.0f;
}

// ---------------------------------------------------------------------------
// Kernel 2: symmetric bf16 tensor-core sim GEMM + exp + rowsum.
// Triangular grid (bj >= bi). CTA: 128x128 tile, 8 warps (2x4), warp 64x32.
// K=256 in 4 slabs of 64 (128B rows, xor swizzle), cp.async double-buffered,
// ONE __syncthreads per slab. Fused exp epilogue -> rowsum[i] (+rowsum[j]).
// ---------------------------------------------------------------------------
#define SLAB_BYTES 16384            // 128 rows x 128B (64 bf16)
#define BUF_BYTES  (2 * SLAB_BYTES) // A + B
#define DYN_SMEM   (2 * BUF_BYTES)  // double buffered = 64 KB

__global__ void __launch_bounds__(256, 2) k_sim() {
    extern __shared__ char dyn_smem[];
    const uint32_t smem = smem_u32(dyn_smem);

    // Triangular decode: blockIdx.x -> (bi, bj), bj >= bi.
    const int id = blockIdx.x;
    int bi = (int)(64.5f - sqrtf(64.5f * 64.5f - 2.0f * (float)id));
    while (bi * NB - bi * (bi - 1) / 2 > id) bi--;
    while ((bi + 1) * NB - (bi + 1) * bi / 2 <= id) bi++;
    const int bj = bi + (id - (bi * NB - bi * (bi - 1) / 2));
    const bool diag = (bi == bj);
    const int i0 = bi * 128, j0 = bj * 128;

    const int tid  = threadIdx.x;
    const int lane = tid & 31;
    const int wid  = tid >> 5;
    const int wm   = wid >> 2;       // 0..1 : warp row  (64 rows each)
    const int wn   = wid & 3;        // 0..3 : warp col  (32 cols each)

    const __nv_bfloat16* Ag = g_znb + (size_t)i0 * DIM;
    const __nv_bfloat16* Bg = g_znb + (size_t)j0 * DIM;

    // gmem->smem: 1024 16B chunks per operand slab; this thread's fixed share.
    const int lr = tid >> 3;                  // base row (r = lr + it*32)
    const int lc = tid & 7;                   // chunk col
    auto issue_slab = [&](int s, int buf) {
        const uint32_t abase = smem + (uint32_t)buf * BUF_BYTES;
        const uint32_t bbase = abase + SLAB_BYTES;
        #pragma unroll
        for (int it = 0; it < 4; it++) {
            const int r = lr + it * 32;
            const uint32_t soff = (uint32_t)(r * 128 + ((lc ^ (r & 7)) << 4));
            CP_ASYNC16(abase + soff, (const char*)(Ag + r * DIM + s * 64 + lc * 8));
            CP_ASYNC16(bbase + soff, (const char*)(Bg + r * DIM + s * 64 + lc * 8));
        }
        CP_COMMIT();
    };

    float acc[4][4][4];
    #pragma unroll
    for (int mt = 0; mt < 4; mt++)
        #pragma unroll
        for (int nt = 0; nt < 4; nt++)
            #pragma unroll
            for (int r = 0; r < 4; r++) acc[mt][nt][r] = 0.0f;

    // ldmatrix per-thread source rows/halves
    const int ar    = lane & 15;                           // A row within 16
    const int ahalf = lane >> 4;                           // A k-half
    const int bn    = ((lane >> 4) & 1) * 8 + (lane & 7);  // B n-row within 16
    const int bhalf = (lane >> 3) & 1;                     // B k-half

    // Precomputed per-thread smem row offsets (row*128 part)
    uint32_t aoff[4], boff[2];
    #pragma unroll
    for (int mt = 0; mt < 4; mt++) {
        const int row = wm * 64 + mt * 16 + ar;
        aoff[mt] = (uint32_t)(row * 128) | ((uint32_t)(row & 7) << 9);  // keep row&7 in bits
    }
    #pragma unroll
    for (int p = 0; p < 2; p++) {
        const int row = wn * 32 + p * 16 + bn;
        boff[p] = (uint32_t)(row * 128) | ((uint32_t)(row & 7) << 9);
    }
    // NOTE: bits [9..11] of row*128 already encode nothing below 128; we stash
    // (row&7) redundantly via the xor done at use time instead:
    #pragma unroll
    for (int mt = 0; mt < 4; mt++) aoff[mt] = (uint32_t)((wm * 64 + mt * 16 + ar) * 128);
    #pragma unroll
    for (int p = 0; p < 2; p++)    boff[p]  = (uint32_t)((wn * 32 + p * 16 + bn) * 128);
    const uint32_t amask[4] = {
        (uint32_t)((wm * 64 + 0 * 16 + ar) & 7),
        (uint32_t)((wm * 64 + 1 * 16 + ar) & 7),
        (uint32_t)((wm * 64 + 2 * 16 + ar) & 7),
        (uint32_t)((wm * 64 + 3 * 16 + ar) & 7)};
    const uint32_t bmask[2] = {
        (uint32_t)((wn * 32 + 0 * 16 + bn) & 7),
        (uint32_t)((wn * 32 + 1 * 16 + bn) & 7)};

    issue_slab(0, 0);

    #pragma unroll 1
    for (int s = 0; s < 4; s++) {
        CP_WAIT(0);
        __syncthreads();                 // slab s visible to all; buffer (s+1)&1 free
        if (s < 3) issue_slab(s + 1, (s + 1) & 1);

        const uint32_t abase = smem + (uint32_t)(s & 1) * BUF_BYTES;
        const uint32_t bbase = abase + SLAB_BYTES;

        #pragma unroll
        for (int kk = 0; kk < 4; kk++) {
            // All fragment loads for this k-step first (6 x ldmatrix.x4)...
            uint32_t bfr[4][2];
            uint32_t afr[4][4];
            #pragma unroll
            for (int p = 0; p < 2; p++) {
                const uint32_t ch = (uint32_t)(kk * 2) + (uint32_t)bhalf;
                const uint32_t ad = bbase + boff[p] + ((ch ^ bmask[p]) << 4);
                LDSM_X4(bfr[2*p][0], bfr[2*p][1], bfr[2*p+1][0], bfr[2*p+1][1], ad);
            }
            #pragma unroll
            for (int mt = 0; mt < 4; mt++) {
                const uint32_t ch = (uint32_t)(kk * 2) + (uint32_t)ahalf;
                const uint32_t ad = abase + aoff[mt] + ((ch ^ amask[mt]) << 4);
                LDSM_X4(afr[mt][0], afr[mt][1], afr[mt][2], afr[mt][3], ad);
            }
            // ...then the 16 MMAs
            #pragma unroll
            for (int mt = 0; mt < 4; mt++)
                #pragma unroll
                for (int nt = 0; nt < 4; nt++)
                    MMA16816(acc[mt][nt][0], acc[mt][nt][1], acc[mt][nt][2], acc[mt][nt][3],
                             afr[mt][0], afr[mt][1], afr[mt][2], afr[mt][3],
                             bfr[nt][0], bfr[nt][1]);
        }
    }

    // ------------------------- epilogue -------------------------
    float rsum[8];   // [mt*2 + h] : rows wm*64 + mt*16 + h*8 + lane/4
    float csum[8];   // [nt*2 + e] : cols wn*32 + nt*8 + (lane%4)*2 + e
    #pragma unroll
    for (int i = 0; i < 8; i++) { rsum[i] = 0.0f; csum[i] = 0.0f; }

    const int q  = lane >> 2;
    const int e2 = (lane & 3) * 2;

    #pragma unroll
    for (int mt = 0; mt < 4; mt++) {
        #pragma unroll
        for (int nt = 0; nt < 4; nt++) {
            #pragma unroll
            for (int r = 0; r < 4; r++) {
                const int h = r >> 1;
                const int e = r & 1;
                float v = ex2(acc[mt][nt][r] * INV_T_LN2);
                if (diag) {
                    const int rl = wm * 64 + mt * 16 + h * 8 + q;
                    const int cl = wn * 32 + nt * 8 + e2 + e;
                    if (rl == cl) v = 0.0f;
                }
                rsum[mt * 2 + h] += v;
                csum[nt * 2 + e] += v;
            }
        }
    }

    #pragma unroll
    for (int i = 0; i < 8; i++) {
        rsum[i] += __shfl_xor_sync(0xffffffffu, rsum[i], 1);
        rsum[i] += __shfl_xor_sync(0xffffffffu, rsum[i], 2);
    }
    #pragma unroll
    for (int i = 0; i < 8; i++) {
        csum[i] += __shfl_xor_sync(0xffffffffu, csum[i], 4);
        csum[i] += __shfl_xor_sync(0xffffffffu, csum[i], 8);
        csum[i] += __shfl_xor_sync(0xffffffffu, csum[i], 16);
    }

    float* sred = reinterpret_cast<float*>(dyn_smem);            // [128][4]
    float* cred = sred + 128 * 4;                                // [128][2]
    __syncthreads();  // done with operand smem

    if ((lane & 3) == 0) {
        #pragma unroll
        for (int i = 0; i < 8; i++) {
            const int mt = i >> 1, h = i & 1;
            const int rl = wm * 64 + mt * 16 + h * 8 + q;
            sred[rl * 4 + wn] = rsum[i];
        }
    }
    if (!diag && (lane >> 2) == 0) {
        #pragma unroll
        for (int i = 0; i < 8; i++) {
            const int nt = i >> 1, e = i & 1;
            const int cl = wn * 32 + nt * 8 + (lane & 3) * 2 + e;
            cred[cl * 2 + wm] = csum[i];
        }
    }
    __syncthreads();

    if (tid < 128) {
        const float v = sred[tid * 4 + 0] + sred[tid * 4 + 1]
                      + sred[tid * 4 + 2] + sred[tid * 4 + 3];
        atomicAdd(&g_rowsum[i0 + tid], v);
        if (!diag) {
            const float w2 = cred[tid * 2 + 0] + cred[tid * 2 + 1];
            atomicAdd(&g_rowsum[j0 + tid], w2);
        }
    }
}

// ---------------------------------------------------------------------------
// Kernel 3: final reduction over rows. loss = mean(log(rowsum) - pos/T).
// ---------------------------------------------------------------------------
__global__ void k_loss(float* __restrict__ out) {
    const int i    = blockIdx.x * 256 + threadIdx.x;
    const int lane = threadIdx.x & 31;
    float val = logf(g_rowsum[i]) - g_pos[i & (BATCH - 1)] * INV_T;
    #pragma unroll
    for (int o = 16; o; o >>= 1) val += __shfl_xor_sync(0xffffffffu, val, o);
    if (lane == 0) atomicAdd(out, val * (1.0f / (float)NROWS));
}

// ---------------------------------------------------------------------------
extern "C" void kernel_launch(void* const* d_in, const int* in_sizes, int n_in,
                              void* d_out, int out_size) {
    const float* z = (const float*)d_in[0];
    float* out = (float*)d_out;

    cudaFuncSetAttribute(k_sim, cudaFuncAttributeMaxDynamicSharedMemorySize, DYN_SMEM);

    k_prep<<<BATCH / 4, 256>>>(z, out);
    k_sim<<<NTRI, 256, DYN_SMEM>>>();
    k_loss<<<NROWS / 256, 256>>>(out);
}

// round 8
// speedup vs baseline: 6.8201x; 1.0338x over previous
#include <cuda_runtime.h>
#include <cuda_bf16.h>
#include <math.h>
#include <stdint.h>

// Problem constants
#define NROWS 8192
#define DIM   256
#define BATCH 4096
#define INV_T      10.0f
#define INV_T_LN2  14.4269504088896340736f

#define NB        64                   // 8192 / 128 tiles per side
#define NTRI      (NB * (NB + 1) / 2)  // 2080 triangular CTAs

// Device-global scratch (no allocations allowed)
__device__ __nv_bfloat16  g_znb[NROWS * DIM];   // normalized rows bf16 (MMA operands)
__device__ float          g_rowsum[NROWS];      // sum_{j!=i} exp(sim_ij)
__device__ float          g_pos[BATCH];         // cos(z_i, z_{i+B})

// ---------------------------------------------------------------------------
__device__ __forceinline__ uint32_t smem_u32(const void* p) {
    uint32_t a;
    asm("{ .reg .u64 t; cvta.to.shared.u64 t, %1; cvt.u32.u64 %0, t; }" : "=r"(a) : "l"(p));
    return a;
}
__device__ __forceinline__ float ex2(float x) {
    asm("ex2.approx.f32 %0, %0;" : "+f"(x));
    return x;
}
#define CP_ASYNC16(s, g) \
    asm volatile("cp.async.cg.shared.global [%0], [%1], 16;" :: "r"(s), "l"(g) : "memory")
#define CP_COMMIT() asm volatile("cp.async.commit_group;" ::: "memory")
#define CP_WAIT(n)  asm volatile("cp.async.wait_group %0;" :: "n"(n) : "memory")

#define LDSM_X4(r0, r1, r2, r3, addr) \
    asm volatile("ldmatrix.sync.aligned.m8n8.x4.shared.b16 {%0,%1,%2,%3}, [%4];" \
                 : "=r"(r0), "=r"(r1), "=r"(r2), "=r"(r3) : "r"(addr))

#define MMA16816(c0, c1, c2, c3, a0, a1, a2, a3, b0, b1) \
    asm volatile("mma.sync.aligned.m16n8k16.row.col.f32.bf16.bf16.f32 " \
                 "{%0,%1,%2,%3}, {%4,%5,%6,%7}, {%8,%9}, {%0,%1,%2,%3};" \
                 : "+f"(c0), "+f"(c1), "+f"(c2), "+f"(c3) \
                 : "r"(a0), "r"(a1), "r"(a2), "r"(a3), "r"(b0), "r"(b1))

// ---------------------------------------------------------------------------
// Kernel 1: one warp per pair (p, p+BATCH): normalize both rows -> g_znb,
// pos dot in registers -> g_pos, zero rowsums.
// ---------------------------------------------------------------------------
__global__ void k_prep(const float* __restrict__ z, float* __restrict__ out) {
    const int w    = threadIdx.x >> 5;
    const int lane = threadIdx.x & 31;
    const int p    = blockIdx.x * 8 + w;

    const float4* za4 = reinterpret_cast<const float4*>(z + (size_t)p * DIM);
    const float4* zb4 = reinterpret_cast<const float4*>(z + (size_t)(p + BATCH) * DIM);
    float4 a0 = za4[lane * 2], a1 = za4[lane * 2 + 1];
    float4 b0 = zb4[lane * 2], b1 = zb4[lane * 2 + 1];

    float ssa = a0.x*a0.x + a0.y*a0.y + a0.z*a0.z + a0.w*a0.w
              + a1.x*a1.x + a1.y*a1.y + a1.z*a1.z + a1.w*a1.w;
    float ssb = b0.x*b0.x + b0.y*b0.y + b0.z*b0.z + b0.w*b0.w
              + b1.x*b1.x + b1.y*b1.y + b1.z*b1.z + b1.w*b1.w;
    float dt  = a0.x*b0.x + a0.y*b0.y + a0.z*b0.z + a0.w*b0.w
              + a1.x*b1.x + a1.y*b1.y + a1.z*b1.z + a1.w*b1.w;
    #pragma unroll
    for (int o = 16; o; o >>= 1) {
        ssa += __shfl_xor_sync(0xffffffffu, ssa, o);
        ssb += __shfl_xor_sync(0xffffffffu, ssb, o);
        dt  += __shfl_xor_sync(0xffffffffu, dt,  o);
    }
    const float sca = rsqrtf(ssa);
    const float scb = rsqrtf(ssb);

    a0.x *= sca; a0.y *= sca; a0.z *= sca; a0.w *= sca;
    a1.x *= sca; a1.y *= sca; a1.z *= sca; a1.w *= sca;
    b0.x *= scb; b0.y *= scb; b0.z *= scb; b0.w *= scb;
    b1.x *= scb; b1.y *= scb; b1.z *= scb; b1.w *= scb;

    __nv_bfloat162 q0 = __floats2bfloat162_rn(a0.x, a0.y);
    __nv_bfloat162 q1 = __floats2bfloat162_rn(a0.z, a0.w);
    __nv_bfloat162 q2 = __floats2bfloat162_rn(a1.x, a1.y);
    __nv_bfloat162 q3 = __floats2bfloat162_rn(a1.z, a1.w);
    uint4 pk;
    pk.x = *reinterpret_cast<uint32_t*>(&q0);
    pk.y = *reinterpret_cast<uint32_t*>(&q1);
    pk.z = *reinterpret_cast<uint32_t*>(&q2);
    pk.w = *reinterpret_cast<uint32_t*>(&q3);
    *reinterpret_cast<uint4*>(g_znb + (size_t)p * DIM + lane * 8) = pk;

    q0 = __floats2bfloat162_rn(b0.x, b0.y);
    q1 = __floats2bfloat162_rn(b0.z, b0.w);
    q2 = __floats2bfloat162_rn(b1.x, b1.y);
    q3 = __floats2bfloat162_rn(b1.z, b1.w);
    pk.x = *reinterpret_cast<uint32_t*>(&q0);
    pk.y = *reinterpret_cast<uint32_t*>(&q1);
    pk.z = *reinterpret_cast<uint32_t*>(&q2);
    pk.w = *reinterpret_cast<uint32_t*>(&q3);
    *reinterpret_cast<uint4*>(g_znb + (size_t)(p + BATCH) * DIM + lane * 8) = pk;

    if (lane == 0) {
        g_pos[p] = dt * sca * scb;
        g_rowsum[p] = 0.0f;
        g_rowsum[p + BATCH] = 0.0f;
        if (p == 0) out[0] = 0.0f;
    }
}

// ---------------------------------------------------------------------------
// Kernel 2: symmetric bf16 tensor-core sim GEMM + exp + rowsum.
// Triangular grid (bj >= bi). CTA: 128x128 tile, 8 warps (2x4), warp 64x32.
// K=256 in 4 slabs of 64, TRIPLE-buffered cp.async; fragments software-
// pipelined (B one k-step ahead, A one m-tile ahead). One sync per slab.
// ---------------------------------------------------------------------------
#define SLAB_BYTES 16384            // 128 rows x 128B (64 bf16)
#define BUF_BYTES  (2 * SLAB_BYTES) // A + B slab
#define DYN_SMEM   (3 * BUF_BYTES + 1024)

__global__ void __launch_bounds__(256, 2) k_sim() {
    extern __shared__ char dyn_smem[];
    const uint32_t smem = (smem_u32(dyn_smem) + 1023u) & ~1023u;

    // Triangular decode: blockIdx.x -> (bi, bj), bj >= bi.
    const int id = blockIdx.x;
    int bi = (int)(64.5f - sqrtf(64.5f * 64.5f - 2.0f * (float)id));
    while (bi * NB - bi * (bi - 1) / 2 > id) bi--;
    while ((bi + 1) * NB - (bi + 1) * bi / 2 <= id) bi++;
    const int bj = bi + (id - (bi * NB - bi * (bi - 1) / 2));
    const bool diag = (bi == bj);
    const int i0 = bi * 128, j0 = bj * 128;

    const int tid  = threadIdx.x;
    const int lane = tid & 31;
    const int wid  = tid >> 5;
    const int wm   = wid >> 2;       // 0..1 : warp row  (64 rows)
    const int wn   = wid & 3;        // 0..3 : warp col  (32 cols)

    const __nv_bfloat16* Ag = g_znb + (size_t)i0 * DIM;
    const __nv_bfloat16* Bg = g_znb + (size_t)j0 * DIM;

    const int lr = tid >> 3;
    const int lc = tid & 7;
    auto issue_slab = [&](int s, int buf) {
        const uint32_t abase = smem + (uint32_t)buf * BUF_BYTES;
        const uint32_t bbase = abase + SLAB_BYTES;
        #pragma unroll
        for (int it = 0; it < 4; it++) {
            const int r = lr + it * 32;
            const uint32_t soff = (uint32_t)(r * 128 + ((lc ^ (r & 7)) << 4));
            CP_ASYNC16(abase + soff, (const char*)(Ag + r * DIM + s * 64 + lc * 8));
            CP_ASYNC16(bbase + soff, (const char*)(Bg + r * DIM + s * 64 + lc * 8));
        }
        CP_COMMIT();
    };

    float acc[4][4][4];
    #pragma unroll
    for (int mt = 0; mt < 4; mt++)
        #pragma unroll
        for (int nt = 0; nt < 4; nt++)
            #pragma unroll
            for (int r = 0; r < 4; r++) acc[mt][nt][r] = 0.0f;

    // ldmatrix per-thread addressing
    const int ar    = lane & 15;
    const int ahalf = lane >> 4;
    const int bn    = ((lane >> 4) & 1) * 8 + (lane & 7);
    const int bhalf = (lane >> 3) & 1;

    uint32_t aoff[4], boff[2], amask[4], bmask[2];
    #pragma unroll
    for (int mt = 0; mt < 4; mt++) {
        const int row = wm * 64 + mt * 16 + ar;
        aoff[mt]  = (uint32_t)(row * 128);
        amask[mt] = (uint32_t)(row & 7);
    }
    #pragma unroll
    for (int p = 0; p < 2; p++) {
        const int row = wn * 32 + p * 16 + bn;
        boff[p]  = (uint32_t)(row * 128);
        bmask[p] = (uint32_t)(row & 7);
    }

    issue_slab(0, 0);
    issue_slab(1, 1);

    uint32_t afr[2][4];       // A frags: double-buffered by m-tile
    uint32_t bfr[2][4][2];    // B frags: double-buffered by k-step

    #pragma unroll 1
    for (int s = 0; s < 4; s++) {
        if (s < 3) { CP_WAIT(1); } else { CP_WAIT(0); }
        __syncthreads();                  // slab s ready; buffer (s+2)%3 free
        if (s < 2) issue_slab(s + 2, (s + 2) % 3);

        const uint32_t abase = smem + (uint32_t)(s % 3) * BUF_BYTES;
        const uint32_t bbase = abase + SLAB_BYTES;

        // Preload k-step 0: B frags (buf 0) + A frags mt=0 (buf 0).
        {
            const uint32_t chb = (uint32_t)bhalf;
            LDSM_X4(bfr[0][0][0], bfr[0][0][1], bfr[0][1][0], bfr[0][1][1],
                    bbase + boff[0] + ((chb ^ bmask[0]) << 4));
            LDSM_X4(bfr[0][2][0], bfr[0][2][1], bfr[0][3][0], bfr[0][3][1],
                    bbase + boff[1] + ((chb ^ bmask[1]) << 4));
            const uint32_t cha = (uint32_t)ahalf;
            LDSM_X4(afr[0][0], afr[0][1], afr[0][2], afr[0][3],
                    abase + aoff[0] + ((cha ^ amask[0]) << 4));
        }

        #pragma unroll
        for (int kk = 0; kk < 4; kk++) {
            const int bc = kk & 1;
            #pragma unroll
            for (int mt = 0; mt < 4; mt++) {
                const int ab = mt & 1;
                // Prefetch next fragments before issuing this group's MMAs.
                if (mt < 3) {
                    const uint32_t cha = (uint32_t)(kk * 2) + (uint32_t)ahalf;
                    LDSM_X4(afr[ab ^ 1][0], afr[ab ^ 1][1], afr[ab ^ 1][2], afr[ab ^ 1][3],
                            abase + aoff[mt + 1] + ((cha ^ amask[mt + 1]) << 4));
                } else if (kk < 3) {
                    const uint32_t chb = (uint32_t)((kk + 1) * 2) + (uint32_t)bhalf;
                    LDSM_X4(bfr[bc ^ 1][0][0], bfr[bc ^ 1][0][1], bfr[bc ^ 1][1][0], bfr[bc ^ 1][1][1],
                            bbase + boff[0] + ((chb ^ bmask[0]) << 4));
                    LDSM_X4(bfr[bc ^ 1][2][0], bfr[bc ^ 1][2][1], bfr[bc ^ 1][3][0], bfr[bc ^ 1][3][1],
                            bbase + boff[1] + ((chb ^ bmask[1]) << 4));
                    const uint32_t cha = (uint32_t)((kk + 1) * 2) + (uint32_t)ahalf;
                    LDSM_X4(afr[ab ^ 1][0], afr[ab ^ 1][1], afr[ab ^ 1][2], afr[ab ^ 1][3],
                            abase + aoff[0] + ((cha ^ amask[0]) << 4));
                }
                #pragma unroll
                for (int nt = 0; nt < 4; nt++)
                    MMA16816(acc[mt][nt][0], acc[mt][nt][1], acc[mt][nt][2], acc[mt][nt][3],
                             afr[ab][0], afr[ab][1], afr[ab][2], afr[ab][3],
                             bfr[bc][nt][0], bfr[bc][nt][1]);
            }
        }
    }

    // ------------------------- epilogue -------------------------
    float rsum[8];   // [mt*2 + h] : rows wm*64 + mt*16 + h*8 + lane/4
    float csum[8];   // [nt*2 + e] : cols wn*32 + nt*8 + (lane%4)*2 + e
    #pragma unroll
    for (int i = 0; i < 8; i++) { rsum[i] = 0.0f; csum[i] = 0.0f; }

    const int q  = lane >> 2;
    const int e2 = (lane & 3) * 2;

    #pragma unroll
    for (int mt = 0; mt < 4; mt++) {
        #pragma unroll
        for (int nt = 0; nt < 4; nt++) {
            #pragma unroll
            for (int r = 0; r < 4; r++) {
                const int h = r >> 1;
                const int e = r & 1;
                float v = ex2(acc[mt][nt][r] * INV_T_LN2);
                if (diag) {
                    const int rl = wm * 64 + mt * 16 + h * 8 + q;
                    const int cl = wn * 32 + nt * 8 + e2 + e;
                    if (rl == cl) v = 0.0f;
                }
                rsum[mt * 2 + h] += v;
                csum[nt * 2 + e] += v;
            }
        }
    }

    #pragma unroll
    for (int i = 0; i < 8; i++) {
        rsum[i] += __shfl_xor_sync(0xffffffffu, rsum[i], 1);
        rsum[i] += __shfl_xor_sync(0xffffffffu, rsum[i], 2);
    }
    #pragma unroll
    for (int i = 0; i < 8; i++) {
        csum[i] += __shfl_xor_sync(0xffffffffu, csum[i], 4);
        csum[i] += __shfl_xor_sync(0xffffffffu, csum[i], 8);
        csum[i] += __shfl_xor_sync(0xffffffffu, csum[i], 16);
    }

    float* sred = reinterpret_cast<float*>(dyn_smem);            // [128][4]
    float* cred = sred + 128 * 4;                                // [128][2]
    __syncthreads();

    if ((lane & 3) == 0) {
        #pragma unroll
        for (int i = 0; i < 8; i++) {
            const int mt = i >> 1, h = i & 1;
            const int rl = wm * 64 + mt * 16 + h * 8 + q;
            sred[rl * 4 + wn] = rsum[i];
        }
    }
    if (!diag && (lane >> 2) == 0) {
        #pragma unroll
        for (int i = 0; i < 8; i++) {
            const int nt = i >> 1, e = i & 1;
            const int cl = wn * 32 + nt * 8 + (lane & 3) * 2 + e;
            cred[cl * 2 + wm] = csum[i];
        }
    }
    __syncthreads();

    if (tid < 128) {
        const float v = sred[tid * 4 + 0] + sred[tid * 4 + 1]
                      + sred[tid * 4 + 2] + sred[tid * 4 + 3];
        atomicAdd(&g_rowsum[i0 + tid], v);
        if (!diag) {
            const float w2 = cred[tid * 2 + 0] + cred[tid * 2 + 1];
            atomicAdd(&g_rowsum[j0 + tid], w2);
        }
    }
}

// ---------------------------------------------------------------------------
// Kernel 3: final reduction. loss = mean(log(rowsum) - pos/T).
// ---------------------------------------------------------------------------
__global__ void k_loss(float* __restrict__ out) {
    const int i    = blockIdx.x * 256 + threadIdx.x;
    const int lane = threadIdx.x & 31;
    float val = logf(g_rowsum[i]) - g_pos[i & (BATCH - 1)] * INV_T;
    #pragma unroll
    for (int o = 16; o; o >>= 1) val += __shfl_xor_sync(0xffffffffu, val, o);
    if (lane == 0) atomicAdd(out, val * (1.0f / (float)NROWS));
}

// ---------------------------------------------------------------------------
extern "C" void kernel_launch(void* const* d_in, const int* in_sizes, int n_in,
                              void* d_out, int out_size) {
    const float* z = (const float*)d_in[0];
    float* out = (float*)d_out;

    cudaFuncSetAttribute(k_sim, cudaFuncAttributeMaxDynamicSharedMemorySize, DYN_SMEM);

    k_prep<<<BATCH / 8, 256>>>(z, out);
    k_sim<<<NTRI, 256, DYN_SMEM>>>();
    k_loss<<<NROWS / 256, 256>>>(out);
}